// round 12
// baseline (speedup 1.0000x reference)
#include <cuda_runtime.h>

#define Bn 8
#define Cn 24
#define Mn 960
#define Wn 15                   // real 64-bit words per row (960/64)
#define WS 16                   // padded words per row
#define ROWS (Bn*Mn)            // 7680

typedef unsigned long long u64;

// Bitmap planes, padded rows (word 15 = 0). g_P2: [5]=r10,[4]=r9,[3]=r8,[2]=r7,[1]=r6,[0]=r4
__device__ ulonglong2 g_F2[ROWS * 8];
__device__ ulonglong2 g_P2[6][ROWS * 8];
// Precombined vertical planes: [0]=W4P9, [1]=W2P8, [2]=D(down), [3]=U(up)
__device__ ulonglong2 g_W2[4][ROWS * 8];

static __device__ __forceinline__ ulonglong2 and2(ulonglong2 a, ulonglong2 b) {
    return make_ulonglong2(a.x & b.x, a.y & b.y);
}

// ── K1: pack + horizontal erosion (row-local, streaming).
#define PR 16
__global__ void __launch_bounds__(256) pack_kernel(const float* __restrict__ in) {
    __shared__ u64 sF[PR][Wn];
    const int lane = threadIdx.x & 31;
    const int warp = threadIdx.x >> 5;
    const int row0 = blockIdx.x * PR;

#pragma unroll
    for (int i = 0; i < PR / 8; i++) {
        int rr = warp + (i << 3);
        int row = row0 + rr;
        int b = row / Mn, y = row - b * Mn;
        const float* p = in + ((size_t)(b * Cn + 1) * Mn + y) * Mn + lane;
        float v[30];
#pragma unroll
        for (int j = 0; j < 30; j++) v[j] = p[j * 32];
        unsigned bb[30];
#pragma unroll
        for (int j = 0; j < 30; j++) bb[j] = __ballot_sync(0xffffffffu, v[j] == 0.0f);
        if (lane < Wn) {
            unsigned lo = 0, hi = 0;
#pragma unroll
            for (int k = 0; k < Wn; k++)
                if (lane == k) { lo = bb[2 * k]; hi = bb[2 * k + 1]; }
            sF[rr][lane] = ((u64)hi << 32) | lo;
        }
    }
    __syncthreads();

    int t = threadIdx.x;
    int rr = t >> 4, w = t & 15;
    int i = (row0 + rr) * WS + w;
    u64* Fw = (u64*)g_F2;
    if (w == Wn) {
        Fw[i] = 0ULL;
#pragma unroll
        for (int p = 0; p < 6; p++) ((u64*)g_P2[p])[i] = 0ULL;
    } else {
        u64 c = sF[rr][w];
        u64 l = (w > 0)      ? sF[rr][w - 1] : 0ULL;
        u64 r = (w < Wn - 1) ? sF[rr][w + 1] : 0ULL;
        Fw[i] = c;
        u64 acc = c;
#pragma unroll
        for (int d = 1; d <= 10; d++) {
            acc &= ((c << d) | (l >> (64 - d))) & ((c >> d) | (r << (64 - d)));
            if (d == 4)       ((u64*)g_P2[0])[i] = acc;
            else if (d == 6)  ((u64*)g_P2[1])[i] = acc;
            else if (d == 7)  ((u64*)g_P2[2])[i] = acc;
            else if (d == 8)  ((u64*)g_P2[3])[i] = acc;
            else if (d == 9)  ((u64*)g_P2[4])[i] = acc;
            else if (d == 10) ((u64*)g_P2[5])[i] = acc;
        }
    }
}

// ── K2: combine — streaming precombination of vertical planes. No smem/barriers.
// One thread per 16B vector (2 words). 13 loads, 4 stores.
__global__ void __launch_bounds__(256) combine_kernel() {
    int t = blockIdx.x * 256 + threadIdx.x;           // 0 .. ROWS*8-1
    int row = t >> 3;
    int v = t & 7;
    int b = row / Mn, y = row - b * Mn;
    // clamped row vector index within same image
    auto J = [&](int yy) {
        yy = yy < 0 ? 0 : (yy > Mn - 1 ? Mn - 1 : yy);
        return (size_t)(b * Mn + yy) * 8 + v;
    };
    ulonglong2 p9a = g_P2[4][J(y)],   p9b = g_P2[4][J(y+1)];
    ulonglong2 p9c = g_P2[4][J(y+2)], p9d = g_P2[4][J(y+3)];
    ulonglong2 p8a = g_P2[3][J(y)],   p8b = g_P2[3][J(y+1)];
    ulonglong2 p7  = g_P2[2][J(y)];
    ulonglong2 p6m = g_P2[1][J(y-1)], p6p = g_P2[1][J(y+1)];
    ulonglong2 p4m = g_P2[0][J(y-2)], p4p = g_P2[0][J(y+2)];
    ulonglong2 fm  = g_F2[J(y-3)],    fp  = g_F2[J(y+3)];
    size_t i = (size_t)row * 8 + v;
    g_W2[0][i] = and2(and2(p9a, p9b), and2(p9c, p9d));   // W4P9
    g_W2[1][i] = and2(p8a, p8b);                          // W2P8
    g_W2[2][i] = and2(and2(p7, p6m), and2(p4m, fm));      // D
    g_W2[3][i] = and2(and2(p7, p6p), and2(p4p, fp));      // U
}

// ── K3: morph — 7-load vertical AND -> border -> LUT float4 expand.
#define RB 8                    // output rows per block; grid = 960
#define NT 240
__global__ void __launch_bounds__(NT, 8) morph_kernel(float* __restrict__ out) {
    __shared__ u64 sE[RB + 2][WS];                    // word 15 zeroed
    __shared__ u64 sB[RB][Wn];
    __shared__ float4 lut[16];
    const int t  = threadIdx.x;
    const int r0 = blockIdx.x * RB;
    const int b  = r0 / Mn;
    const int y0 = r0 - b * Mn;

    if (t < 16)
        lut[t] = make_float4(t & 1 ? 1.0f : 0.0f, t & 2 ? 1.0f : 0.0f,
                             t & 4 ? 1.0f : 0.0f, t & 8 ? 1.0f : 0.0f);

    // Phase B: eroded rows y0-1 .. y0+RB (150 tasks) + zero 10 pad words.
    if (t < (RB + 2) * Wn) {
        int rr = t / Wn, w = t - rr * Wn;
        int y = y0 + rr - 1;
        u64 e = 0ULL;
        if (y >= 10 && y <= Mn - 11) {
            size_t i = (size_t)(b * Mn + y) * WS + w;
            u64 v0 = ((const u64*)g_P2[5])[i];              // P10[y]
            u64 v1 = ((const u64*)g_W2[0])[i - 4*WS];       // W4P9[y-4]
            u64 v2 = ((const u64*)g_W2[0])[i + 1*WS];       // W4P9[y+1]
            u64 v3 = ((const u64*)g_W2[1])[i - 6*WS];       // W2P8[y-6]
            u64 v4 = ((const u64*)g_W2[1])[i + 5*WS];       // W2P8[y+5]
            u64 v5 = ((const u64*)g_W2[2])[i - 7*WS];       // D[y-7]
            u64 v6 = ((const u64*)g_W2[3])[i + 7*WS];       // U[y+7]
            e = ((v0 & v1) & (v2 & v3)) & ((v4 & v5) & v6);
        }
        sE[rr][w] = e;
    } else if (t < (RB + 2) * Wn + (RB + 2)) {
        sE[t - (RB + 2) * Wn][Wn] = 0ULL;             // pad words
    }
    __syncthreads();

    // Phase C: border = dilate(e, cross) & ~e (120 tasks).
    if (t < RB * Wn) {
        int rr = t / Wn, w = t - rr * Wn;
        u64 e  = sE[rr + 1][w];
        u64 eu = sE[rr][w];
        u64 ed = sE[rr + 2][w];
        u64 l  = (w > 0) ? sE[rr + 1][w - 1] : 0ULL;
        u64 r  = sE[rr + 1][w + 1];                   // pad word is 0 at w=14
        u64 d = e | eu | ed | (e << 1) | (l >> 63) | (e >> 1) | (r << 63);
        sB[rr][w] = d & ~e;
    }
    __syncthreads();

    // Phase D: bits -> float4 via LUT; row = loop constant, column = t.
    const int w  = t >> 4;
    const int sh = (t & 15) << 2;
    float4* o = (float4*)out + (size_t)r0 * 240 + t;
#pragma unroll
    for (int k = 0; k < RB; k++) {
        unsigned nib = (unsigned)(sB[k][w] >> sh) & 15u;
        o[(size_t)k * 240] = lut[nib];
    }
}

extern "C" void kernel_launch(void* const* d_in, const int* in_sizes, int n_in,
                              void* d_out, int out_size) {
    const float* map_features = (const float*)d_in[0];
    float* out = (float*)d_out;
    pack_kernel<<<ROWS / PR, 256>>>(map_features);      // 480 blocks
    combine_kernel<<<(ROWS * 8) / 256, 256>>>();        // 240 blocks
    morph_kernel<<<ROWS / RB, NT>>>(out);               // 960 blocks
}

// round 13
// speedup vs baseline: 1.1196x; 1.1196x over previous
#include <cuda_runtime.h>

#define Bn 8
#define Cn 24
#define Mn 960
#define Wn 15                   // real 64-bit words per row (960/64)
#define WS 16                   // padded words per row
#define ROWS (Bn*Mn)            // 7680

typedef unsigned long long u64;

// Combined vertical planes (padded rows, word 15 = 0):
// g_P10[y]  = hrode_r10(row y)
// g_W[0][y] = AND of hrode_r9 rows y..y+3          (W4P9)
// g_W[1][y] = AND of hrode_r8 rows y, y+1          (W2P8)
// g_W[2][y] = r7[y] & r6[y-1] & r4[y-2] & F[y-3]   (D)
// g_W[3][y] = r7[y] & r6[y+1] & r4[y+2] & F[y+3]   (U)
// eroded[y] = P10[y] & W4P9[y-4] & W4P9[y+1] & W2P8[y-6] & W2P8[y+5] & D[y-7] & U[y+7]
__device__ u64 g_P10[ROWS * WS];
__device__ u64 g_W[4][ROWS * WS];

// ── K1: pack + hrode + vertical precombine. One block = 16 output rows,
// ballots 22 rows (±3 halo), all planes staged in smem, writes 5 planes.
#define PR 16
#define RT (PR + 6)             // 22 staged rows
__global__ void __launch_bounds__(256) pack_kernel(const float* __restrict__ in) {
    __shared__ u64 sF[RT][Wn], sP4[RT][Wn], sP6[RT][Wn], sP7[RT][Wn],
                   sP8[RT][Wn], sP9[RT][Wn], sP10[RT][Wn];
    const int t    = threadIdx.x;
    const int lane = t & 31;
    const int warp = t >> 5;
    const int row0 = blockIdx.x * PR;                 // global row = b*Mn + y
    const int b    = row0 / Mn;
    const int y0   = row0 - b * Mn;

    // Phase 0: ballot-pack rows y0-3 .. y0+18 (zero outside image)
    for (int rr = warp; rr < RT; rr += 8) {
        int y = y0 + rr - 3;
        if (y >= 0 && y < Mn) {
            const float* p = in + ((size_t)(b * Cn + 1) * Mn + y) * Mn + lane;
            float v[30];
#pragma unroll
            for (int j = 0; j < 30; j++) v[j] = p[j * 32];
            unsigned bb[30];
#pragma unroll
            for (int j = 0; j < 30; j++) bb[j] = __ballot_sync(0xffffffffu, v[j] == 0.0f);
            if (lane < Wn) {
                unsigned lo = 0, hi = 0;
#pragma unroll
                for (int k = 0; k < Wn; k++)
                    if (lane == k) { lo = bb[2 * k]; hi = bb[2 * k + 1]; }
                sF[rr][lane] = ((u64)hi << 32) | lo;
            }
        } else if (lane < Wn) {
            sF[rr][lane] = 0ULL;
        }
    }
    __syncthreads();

    // Phase A: horizontal erosions for all staged rows (330 tasks)
    for (int task = t; task < RT * Wn; task += 256) {
        int rr = task / Wn, w = task - rr * Wn;
        u64 c = sF[rr][w];
        u64 l = (w > 0)      ? sF[rr][w - 1] : 0ULL;
        u64 r = (w < Wn - 1) ? sF[rr][w + 1] : 0ULL;
        u64 acc = c;
#pragma unroll
        for (int d = 1; d <= 10; d++) {
            acc &= ((c << d) | (l >> (64 - d))) & ((c >> d) | (r << (64 - d)));
            if (d == 4)       sP4[rr][w] = acc;
            else if (d == 6)  sP6[rr][w] = acc;
            else if (d == 7)  sP7[rr][w] = acc;
            else if (d == 8)  sP8[rr][w] = acc;
            else if (d == 9)  sP9[rr][w] = acc;
            else if (d == 10) sP10[rr][w] = acc;
        }
    }
    __syncthreads();

    // Phase B: vertical precombine + store (240 real tasks + 16 pad tasks)
    if (t < PR * Wn) {
        int rr = t / Wn, w = t - rr * Wn;
        int h = rr + 3;                               // smem row of output row
        size_t i = (size_t)(row0 + rr) * WS + w;
        g_P10[i]  = sP10[h][w];
        g_W[0][i] = (sP9[h][w] & sP9[h+1][w]) & (sP9[h+2][w] & sP9[h+3][w]);
        g_W[1][i] = sP8[h][w] & sP8[h+1][w];
        g_W[2][i] = (sP7[h][w] & sP6[h-1][w]) & (sP4[h-2][w] & sF[h-3][w]);
        g_W[3][i] = (sP7[h][w] & sP6[h+1][w]) & (sP4[h+2][w] & sF[h+3][w]);
    } else if (t < PR * Wn + PR) {
        size_t i = (size_t)(row0 + (t - PR * Wn)) * WS + Wn;   // pad word
        g_P10[i] = 0ULL;
        g_W[0][i] = 0ULL; g_W[1][i] = 0ULL; g_W[2][i] = 0ULL; g_W[3][i] = 0ULL;
    }
}

// ── K2: morph — 7-load vertical AND -> cross border -> LUT float4 expand.
#define RB 8                    // output rows per block; grid = 960
#define NT 240
__global__ void __launch_bounds__(NT, 8) morph_kernel(float* __restrict__ out) {
    __shared__ u64 sE[RB + 2][WS];                    // word 15 zeroed
    __shared__ u64 sB[RB][Wn];
    __shared__ float4 lut[16];
    const int t  = threadIdx.x;
    const int r0 = blockIdx.x * RB;
    const int b  = r0 / Mn;
    const int y0 = r0 - b * Mn;

    if (t < 16)
        lut[t] = make_float4(t & 1 ? 1.0f : 0.0f, t & 2 ? 1.0f : 0.0f,
                             t & 4 ? 1.0f : 0.0f, t & 8 ? 1.0f : 0.0f);

    // Phase B: eroded rows y0-1 .. y0+RB (150 tasks) + zero 10 pad words.
    if (t < (RB + 2) * Wn) {
        int rr = t / Wn, w = t - rr * Wn;
        int y = y0 + rr - 1;
        u64 e = 0ULL;
        if (y >= 10 && y <= Mn - 11) {
            size_t i = (size_t)(b * Mn + y) * WS + w;
            u64 v0 = g_P10[i];
            u64 v1 = g_W[0][i - 4*WS];                // W4P9[y-4]
            u64 v2 = g_W[0][i + 1*WS];                // W4P9[y+1]
            u64 v3 = g_W[1][i - 6*WS];                // W2P8[y-6]
            u64 v4 = g_W[1][i + 5*WS];                // W2P8[y+5]
            u64 v5 = g_W[2][i - 7*WS];                // D[y-7]
            u64 v6 = g_W[3][i + 7*WS];                // U[y+7]
            e = ((v0 & v1) & (v2 & v3)) & ((v4 & v5) & v6);
        }
        sE[rr][w] = e;
    } else if (t < (RB + 2) * Wn + (RB + 2)) {
        sE[t - (RB + 2) * Wn][Wn] = 0ULL;             // pad words
    }
    __syncthreads();

    // Phase C: border = dilate(e, cross) & ~e (120 tasks).
    if (t < RB * Wn) {
        int rr = t / Wn, w = t - rr * Wn;
        u64 e  = sE[rr + 1][w];
        u64 eu = sE[rr][w];
        u64 ed = sE[rr + 2][w];
        u64 l  = (w > 0) ? sE[rr + 1][w - 1] : 0ULL;
        u64 r  = sE[rr + 1][w + 1];                   // pad word is 0 at w=14
        u64 d = e | eu | ed | (e << 1) | (l >> 63) | (e >> 1) | (r << 63);
        sB[rr][w] = d & ~e;
    }
    __syncthreads();

    // Phase D: bits -> float4 via LUT; row = loop constant, column = t.
    const int w  = t >> 4;
    const int sh = (t & 15) << 2;
    float4* o = (float4*)out + (size_t)r0 * 240 + t;
#pragma unroll
    for (int k = 0; k < RB; k++) {
        unsigned nib = (unsigned)(sB[k][w] >> sh) & 15u;
        o[(size_t)k * 240] = lut[nib];
    }
}

extern "C" void kernel_launch(void* const* d_in, const int* in_sizes, int n_in,
                              void* d_out, int out_size) {
    const float* map_features = (const float*)d_in[0];
    float* out = (float*)d_out;
    pack_kernel<<<ROWS / PR, 256>>>(map_features);    // 480 blocks
    morph_kernel<<<ROWS / RB, NT>>>(out);             // 960 blocks
}

// round 14
// speedup vs baseline: 1.2937x; 1.1555x over previous
#include <cuda_runtime.h>

#define Bn 8
#define Cn 24
#define Mn 960
#define Wn 15                   // 64-bit words per row (960/64)
#define ROWS (Bn*Mn)            // 7680
#define NW (ROWS*Wn)            // 115200 words
#define TPI 60                  // 16-row tiles per image (960/16)
#define NTILE (ROWS/16)         // 480 tiles

typedef unsigned long long u64;

// Global bitmap planes: frontier + hrode r = 4,6,7,8,9,10 (unpadded, Wn stride).
__device__ u64 g_F[NW];
__device__ u64 g_P[6][NW];
// Handshake flags (zero-init; consumed slots are reset to 0 by their single consumer).
__device__ int g_flag0[NTILE];  // set by tile i, consumed by tile i+1
__device__ int g_flag1[NTILE];  // set by tile i, consumed by tile i-1

// Fused kernel: each block = one 16-row tile. pack -> hrode -> flag -> spin on
// vertical neighbors -> vertical AND -> border -> LUT float4 expand.
__global__ void __launch_bounds__(256, 4) fused_kernel(const float* __restrict__ in,
                                                       float* __restrict__ out) {
    __shared__ u64 sF[16][Wn];
    __shared__ u64 sE[18][16];                        // eroded rows (±1), word 15 = 0
    __shared__ u64 sB[16][Wn];
    __shared__ float4 lut[16];

    const int t    = threadIdx.x;
    const int lane = t & 31;
    const int warp = t >> 5;
    const int tile = blockIdx.x;
    const int ii   = tile % TPI;                      // tile index within image
    const int row0 = tile * 16;                       // global row = b*Mn + y
    const int b    = row0 / Mn;
    const int y0   = row0 - b * Mn;

    if (t < 16)
        lut[t] = make_float4(t & 1 ? 1.0f : 0.0f, t & 2 ? 1.0f : 0.0f,
                             t & 4 ? 1.0f : 0.0f, t & 8 ? 1.0f : 0.0f);

    // ── pack: ballot 16 rows (8 warps x 2 rows)
#pragma unroll
    for (int i = 0; i < 2; i++) {
        int rr = warp + (i << 3);
        int y = y0 + rr;
        const float* p = in + ((size_t)(b * Cn + 1) * Mn + y) * Mn + lane;
        float v[30];
#pragma unroll
        for (int j = 0; j < 30; j++) v[j] = p[j * 32];
        unsigned bb[30];
#pragma unroll
        for (int j = 0; j < 30; j++) bb[j] = __ballot_sync(0xffffffffu, v[j] == 0.0f);
        if (lane < Wn) {
            unsigned lo = 0, hi = 0;
#pragma unroll
            for (int k = 0; k < Wn; k++)
                if (lane == k) { lo = bb[2 * k]; hi = bb[2 * k + 1]; }
            sF[rr][lane] = ((u64)hi << 32) | lo;
        }
    }
    __syncthreads();

    // ── hrode: 240 tasks, write 7 planes to global
    if (t < 16 * Wn) {
        int rr = t / Wn, w = t - rr * Wn;
        u64 c = sF[rr][w];
        u64 l = (w > 0)      ? sF[rr][w - 1] : 0ULL;
        u64 r = (w < Wn - 1) ? sF[rr][w + 1] : 0ULL;
        int i = (row0 + rr) * Wn + w;
        g_F[i] = c;
        u64 acc = c;
#pragma unroll
        for (int d = 1; d <= 10; d++) {
            acc &= ((c << d) | (l >> (64 - d))) & ((c >> d) | (r << (64 - d)));
            if (d == 4)       g_P[0][i] = acc;
            else if (d == 6)  g_P[1][i] = acc;
            else if (d == 7)  g_P[2][i] = acc;
            else if (d == 8)  g_P[3][i] = acc;
            else if (d == 9)  g_P[4][i] = acc;
            else if (d == 10) g_P[5][i] = acc;
        }
    }
    __syncthreads();

    // ── publish + wait for vertical neighbors (tid 0 spins; capacity > grid, no deadlock)
    if (t == 0) {
        __threadfence();
        atomicExch(&g_flag0[tile], 1);
        atomicExch(&g_flag1[tile], 1);
        if (ii > 0)       while (atomicAdd(&g_flag0[tile - 1], 0) == 0) {}
        if (ii < TPI - 1) while (atomicAdd(&g_flag1[tile + 1], 0) == 0) {}
        __threadfence();
    }
    __syncthreads();

    // ── vertical 21-term AND: eroded rows y0-1 .. y0+16 (270 tasks) + zero pads
    if (t < 18) sE[t][15] = 0ULL;
    for (int task = t; task < 18 * Wn; task += 256) {
        int rr = task / Wn, w = task - rr * Wn;
        int y = y0 + rr - 1;
        u64 e = 0ULL;
        if (y >= 10 && y <= Mn - 11) {
            int i = (b * Mn + y) * Wn + w;
            u64 v0  = g_P[5][i];
            u64 v1  = g_P[4][i - 1*Wn];  u64 v2  = g_P[4][i + 1*Wn];
            u64 v3  = g_P[4][i - 2*Wn];  u64 v4  = g_P[4][i + 2*Wn];
            u64 v5  = g_P[4][i - 3*Wn];  u64 v6  = g_P[4][i + 3*Wn];
            u64 v7  = g_P[4][i - 4*Wn];  u64 v8  = g_P[4][i + 4*Wn];
            u64 v9  = g_P[3][i - 5*Wn];  u64 v10 = g_P[3][i + 5*Wn];
            u64 v11 = g_P[3][i - 6*Wn];  u64 v12 = g_P[3][i + 6*Wn];
            u64 v13 = g_P[2][i - 7*Wn];  u64 v14 = g_P[2][i + 7*Wn];
            u64 v15 = g_P[1][i - 8*Wn];  u64 v16 = g_P[1][i + 8*Wn];
            u64 v17 = g_P[0][i - 9*Wn];  u64 v18 = g_P[0][i + 9*Wn];
            u64 v19 = g_F[i - 10*Wn];    u64 v20 = g_F[i + 10*Wn];
            u64 a0 = (v0 & v1) & (v2 & v3);
            u64 a1 = (v4 & v5) & (v6 & v7);
            u64 a2 = (v8 & v9) & (v10 & v11);
            u64 a3 = (v12 & v13) & (v14 & v15);
            u64 a4 = (v16 & v17) & (v18 & v19);
            e = ((a0 & a1) & (a2 & a3)) & (a4 & v20);
        }
        sE[rr][w] = e;
    }
    __syncthreads();

    // ── release consumed flags (all neighbor reads complete)
    if (t == 0) {
        if (ii > 0)       atomicExch(&g_flag0[tile - 1], 0);
        if (ii < TPI - 1) atomicExch(&g_flag1[tile + 1], 0);
    }

    // ── border = dilate(e, cross) & ~e (240 tasks)
    if (t < 16 * Wn) {
        int rr = t / Wn, w = t - rr * Wn;
        u64 e  = sE[rr + 1][w];
        u64 eu = sE[rr][w];
        u64 ed = sE[rr + 2][w];
        u64 l  = (w > 0) ? sE[rr + 1][w - 1] : 0ULL;
        u64 r  = sE[rr + 1][w + 1];                   // pad word 0 at w=14
        u64 d = e | eu | ed | (e << 1) | (l >> 63) | (e >> 1) | (r << 63);
        sB[rr][w] = d & ~e;
    }
    __syncthreads();

    // ── expand: 16 rows x 240 float4; row = loop constant, col = t (t<240)
    if (t < 240) {
        const int w  = t >> 4;
        const int sh = (t & 15) << 2;
        float4* o = (float4*)out + (size_t)row0 * 240 + t;
#pragma unroll
        for (int k = 0; k < 16; k++) {
            unsigned nib = (unsigned)(sB[k][w] >> sh) & 15u;
            o[(size_t)k * 240] = lut[nib];
        }
    }
}

extern "C" void kernel_launch(void* const* d_in, const int* in_sizes, int n_in,
                              void* d_out, int out_size) {
    const float* map_features = (const float*)d_in[0];
    float* out = (float*)d_out;
    fused_kernel<<<NTILE, 256>>>(map_features, out);  // 480 blocks, single launch
}